// round 9
// baseline (speedup 1.0000x reference)
#include <cuda_runtime.h>
#include <cuda_fp16.h>
#include <cstdint>

#define DI __device__ __forceinline__

constexpr int NB = 16, SEQ = 4096, INF = 1024, OUTF = 1024, RR = 16, NSK = 16;
constexpr int MTOT = NB * SEQ;                    // 65536

// ---------------- device scratch (allocation-free) ----------------
__device__ __half d_A16[(size_t)MTOT * INF];      // 134 MB
__device__ __half d_Weff[(size_t)NB * OUTF * INF];// 32 MB, [b][n][k] K-major
__device__ float  d_wA[NB * INF * RR];
__device__ float  d_wB[NB * RR * OUTF];

// ---------------- prep kernels ----------------
__global__ void k_convert(const float4* __restrict__ in) {
    size_t i = ((size_t)blockIdx.x * 256 + threadIdx.x) * 2;   // < 16777216
    float4 v0 = in[i];
    float4 v1 = in[i + 1];
    __half2 h0 = __floats2half2_rn(v0.x, v0.y);
    __half2 h1 = __floats2half2_rn(v0.z, v0.w);
    __half2 h2 = __floats2half2_rn(v1.x, v1.y);
    __half2 h3 = __floats2half2_rn(v1.z, v1.w);
    uint4 u;
    u.x = *reinterpret_cast<uint32_t*>(&h0);
    u.y = *reinterpret_cast<uint32_t*>(&h1);
    u.z = *reinterpret_cast<uint32_t*>(&h2);
    u.w = *reinterpret_cast<uint32_t*>(&h3);
    reinterpret_cast<uint4*>(d_A16)[i >> 1] = u;
}

__global__ void k_wAB(const float* __restrict__ A, const float* __restrict__ Bm,
                      const float* __restrict__ sl, const int* __restrict__ tid_) {
    int gid = blockIdx.x * 256 + threadIdx.x;     // < 524288
    int hi = gid >> 18, e = gid & 262143;
    int b = e >> 14, j = e & 16383;
    __shared__ float lg[NSK];
    __shared__ float ssum;
    if (threadIdx.x < NSK) {
        float v = 1.f / (1.f + expf(-sl[tid_[b] * NSK + threadIdx.x]));
        lg[threadIdx.x] = v;
    }
    __syncthreads();
    if (threadIdx.x == 0) {
        float s = 0.f;
#pragma unroll
        for (int k = 0; k < NSK; ++k) s += lg[k];
        ssum = 1.f / (s + 1e-12f);
    }
    __syncthreads();
    const float* src = hi ? Bm : A;
    float acc = 0.f;
#pragma unroll
    for (int s = 0; s < NSK; ++s) acc += lg[s] * src[s * 16384 + j];
    acc *= ssum;
    if (hi) d_wB[e] = acc; else d_wA[e] = acc;
}

__global__ void __launch_bounds__(256) k_weff(const float* __restrict__ weight) {
    int b = blockIdx.x >> 4, ot = blockIdx.x & 15;
    __shared__ float wBs[64 * RR];                 // [o_local][r]
    for (int t = threadIdx.x; t < 64 * RR; t += 256) {
        int ol = t >> 4, r = t & 15;
        wBs[t] = d_wB[b * 16384 + r * OUTF + ot * 64 + ol];
    }
    __syncthreads();
    const int i0 = threadIdx.x * 4;
    float wa[4][RR];
#pragma unroll
    for (int ii = 0; ii < 4; ++ii) {
        float4 v0 = *(const float4*)(d_wA + b * 16384 + (i0 + ii) * RR);
        float4 v1 = *(const float4*)(d_wA + b * 16384 + (i0 + ii) * RR + 4);
        float4 v2 = *(const float4*)(d_wA + b * 16384 + (i0 + ii) * RR + 8);
        float4 v3 = *(const float4*)(d_wA + b * 16384 + (i0 + ii) * RR + 12);
        wa[ii][0]=v0.x; wa[ii][1]=v0.y; wa[ii][2]=v0.z; wa[ii][3]=v0.w;
        wa[ii][4]=v1.x; wa[ii][5]=v1.y; wa[ii][6]=v1.z; wa[ii][7]=v1.w;
        wa[ii][8]=v2.x; wa[ii][9]=v2.y; wa[ii][10]=v2.z; wa[ii][11]=v2.w;
        wa[ii][12]=v3.x; wa[ii][13]=v3.y; wa[ii][14]=v3.z; wa[ii][15]=v3.w;
    }
#pragma unroll 4
    for (int ol = 0; ol < 64; ++ol) {
        int o = ot * 64 + ol;
        float4 w = *(const float4*)(weight + (size_t)o * INF + i0);
        float acc[4] = {0.f, 0.f, 0.f, 0.f};
#pragma unroll
        for (int r = 0; r < RR; ++r) {
            float wb = wBs[ol * RR + r];
            acc[0] += wa[0][r] * wb; acc[1] += wa[1][r] * wb;
            acc[2] += wa[2][r] * wb; acc[3] += wa[3][r] * wb;
        }
        __half2 h0 = __floats2half2_rn(w.x + acc[0] * (1.f / RR), w.y + acc[1] * (1.f / RR));
        __half2 h1 = __floats2half2_rn(w.z + acc[2] * (1.f / RR), w.w + acc[3] * (1.f / RR));
        uint2 u;
        u.x = *reinterpret_cast<uint32_t*>(&h0);
        u.y = *reinterpret_cast<uint32_t*>(&h1);
        *reinterpret_cast<uint2*>(d_Weff + (size_t)b * (OUTF * INF) + (size_t)o * INF + i0) = u;
    }
}

// ---------------- GEMM config ----------------
constexpr int BM = 128, BN = 128, BK = 64;        // K chunk = 64 halfs = 128 B rows
constexpr int NCHUNK = INF / BK;                  // 16
constexpr int STAGE_BYTES = 32768;                // A 16K + B 16K
constexpr int SM_B = 16384;
constexpr int SMEM_TOTAL = 1024 + 3 * STAGE_BYTES;   // 99328 (2 CTAs/SM)

DI uint32_t s2u(const void* p) {
    uint32_t a;
    asm("{ .reg .u64 t; cvta.to.shared.u64 t, %1; cvt.u32.u64 %0, t; }" : "=r"(a) : "l"(p));
    return a;
}
DI void cp16(uint32_t dst, const void* src) {
    asm volatile("cp.async.cg.shared.global [%0], [%1], 16;" :: "r"(dst), "l"(src));
}
DI void cp_commit() { asm volatile("cp.async.commit_group;" ::: "memory"); }
template <int N> DI void cp_wait() { asm volatile("cp.async.wait_group %0;" :: "n"(N) : "memory"); }

DI void ldsm4(uint32_t addr, uint32_t* r) {
    asm volatile("ldmatrix.sync.aligned.m8n8.x4.shared.b16 {%0,%1,%2,%3}, [%4];"
                 : "=r"(r[0]), "=r"(r[1]), "=r"(r[2]), "=r"(r[3]) : "r"(addr));
}
DI void mma16816(float* c, const uint32_t* a, const uint32_t* b) {
    asm volatile(
        "mma.sync.aligned.m16n8k16.row.col.f32.f16.f16.f32 "
        "{%0,%1,%2,%3}, {%4,%5,%6,%7}, {%8,%9}, {%0,%1,%2,%3};"
        : "+f"(c[0]), "+f"(c[1]), "+f"(c[2]), "+f"(c[3])
        : "r"(a[0]), "r"(a[1]), "r"(a[2]), "r"(a[3]), "r"(b[0]), "r"(b[1]));
}

// full stage fill (prologue only), 128 threads
DI void fill_stage(uint32_t stg, const __half* Aptr, const __half* Bptr, int tid) {
#pragma unroll
    for (int j = 0; j < 8; ++j) {
        int idx = tid + j * 128;
        int row = idx >> 3, seg = idx & 7;
        uint32_t off = row * 128 + ((seg * 16) ^ ((row & 7) << 4));
        cp16(stg + off, Aptr + row * 1024 + seg * 8);
    }
#pragma unroll
    for (int j = 0; j < 8; ++j) {
        int idx = tid + j * 128;
        int row = idx >> 3, seg = idx & 7;
        uint32_t off = row * 128 + ((seg * 16) ^ ((row & 7) << 4));
        cp16(stg + SM_B + off, Bptr + row * 1024 + seg * 8);
    }
    cp_commit();
}

// quarter fill: part q in [0,4): q<2 -> A half-q, q>=2 -> B half-(q-2)
DI void fill_quarter(uint32_t stg, const __half* Aptr, const __half* Bptr, int tid, int q) {
    uint32_t base = (q < 2) ? stg : (stg + SM_B);
    const __half* src = (q < 2) ? Aptr : Bptr;
    int j0 = (q & 1) * 4;
#pragma unroll
    for (int j = 0; j < 4; ++j) {
        int idx = tid + (j0 + j) * 128;
        int row = idx >> 3, seg = idx & 7;
        uint32_t off = row * 128 + ((seg * 16) ^ ((row & 7) << 4));
        cp16(base + off, src + row * 1024 + seg * 8);
    }
}

// ---------------- GEMM kernel (mma.sync, 64x64 warp tiles, 2 CTAs/SM,
//                  fill interleaved into the kk loop) ----------------
__global__ void __launch_bounds__(128, 2)
k_gemm(const float* __restrict__ bias, float* __restrict__ out) {
    extern __shared__ char smem_raw[];
    uint32_t sb = (s2u(smem_raw) + 1023u) & ~1023u;
    const int tid = threadIdx.x, lane = tid & 31, w = tid >> 5;
    const int wm = w >> 1, wn = w & 1;            // warp tile 64x64 in 2x2 grid
    const int m0 = blockIdx.y * BM;
    const int n0 = blockIdx.x * BN;
    const int b  = m0 >> 12;

    const __half* Abase = d_A16 + (size_t)m0 * INF;
    const __half* Bbase = d_Weff + (size_t)b * (OUTF * INF) + (size_t)n0 * INF;

    fill_stage(sb, Abase, Bbase, tid);
    fill_stage(sb + STAGE_BYTES, Abase + BK, Bbase + BK, tid);

    float c[4][8][4];
#pragma unroll
    for (int i = 0; i < 4; ++i)
#pragma unroll
        for (int j = 0; j < 8; ++j)
#pragma unroll
            for (int q = 0; q < 4; ++q) c[i][j][q] = 0.f;

    const int a_row = wm * 64 + (lane & 15);                      // + mt*16
    const int a_kb  = (lane >> 4) * 16;
    const int b_row = wn * 64 + ((lane >> 4) << 3) + (lane & 7);  // + p*16
    const int b_kb  = ((lane >> 3) & 1) * 16;

    int st = 0, fs = 2;
#pragma unroll 1
    for (int i = 0; i < NCHUNK; ++i) {
        if (i < NCHUNK - 1) cp_wait<1>();
        else cp_wait<0>();
        __syncthreads();

        uint32_t as = sb + st * STAGE_BYTES;
        uint32_t bs = as + SM_B;
        uint32_t nstg = sb + fs * STAGE_BYTES;
        const __half* Anext = Abase + (i + 2) * BK;
        const __half* Bnext = Bbase + (i + 2) * BK;
        bool do_fill = (i + 2 < NCHUNK);

#pragma unroll
        for (int kk = 0; kk < 4; ++kk) {
            uint32_t af[4][4], bf[8][2];
#pragma unroll
            for (int mt = 0; mt < 4; ++mt) {
                int row = a_row + mt * 16;
                ldsm4(as + row * 128 + ((kk * 32 + a_kb) ^ ((row & 7) << 4)), af[mt]);
            }
#pragma unroll
            for (int p = 0; p < 4; ++p) {
                int row = b_row + p * 16;
                uint32_t r[4];
                ldsm4(bs + row * 128 + ((kk * 32 + b_kb) ^ ((row & 7) << 4)), r);
                bf[p * 2][0] = r[0]; bf[p * 2][1] = r[1];
                bf[p * 2 + 1][0] = r[2]; bf[p * 2 + 1][1] = r[3];
            }
            // interleave 1/4 of the next-next stage fill between LDSM and MMA drain
            if (do_fill) fill_quarter(nstg, Anext, Bnext, tid, kk);
#pragma unroll
            for (int mt = 0; mt < 4; ++mt)
#pragma unroll
                for (int nt = 0; nt < 8; ++nt)
                    mma16816(c[mt][nt], af[mt], bf[nt]);
        }
        if (do_fill) cp_commit();
        st = (st == 2) ? 0 : st + 1;
        fs = (fs == 2) ? 0 : fs + 1;
    }

    // ---- epilogue ----
#pragma unroll
    for (int mt = 0; mt < 4; ++mt) {
        int r0 = m0 + wm * 64 + mt * 16 + (lane >> 2);
#pragma unroll
        for (int nt = 0; nt < 8; ++nt) {
            int cn = n0 + wn * 64 + nt * 8 + (lane & 3) * 2;
            float bx = __ldg(bias + cn), by = __ldg(bias + cn + 1);
            float2 v0 = make_float2(c[mt][nt][0] + bx, c[mt][nt][1] + by);
            float2 v1 = make_float2(c[mt][nt][2] + bx, c[mt][nt][3] + by);
            *reinterpret_cast<float2*>(out + (size_t)r0 * OUTF + cn) = v0;
            *reinterpret_cast<float2*>(out + (size_t)(r0 + 8) * OUTF + cn) = v1;
        }
    }
}

// ---------------- launch ----------------
extern "C" void kernel_launch(void* const* d_in, const int* in_sizes, int n_in,
                              void* d_out, int out_size) {
    const float* input  = (const float*)d_in[0];
    const float* slog   = (const float*)d_in[1];
    const float* weight = (const float*)d_in[2];
    const float* bias   = (const float*)d_in[3];
    const float* swA    = (const float*)d_in[4];
    const float* swB    = (const float*)d_in[5];
    const int*   tids   = (const int*)d_in[6];
    float* out = (float*)d_out;

    cudaFuncSetAttribute(k_gemm, cudaFuncAttributeMaxDynamicSharedMemorySize, SMEM_TOTAL);

    k_convert<<<32768, 256>>>((const float4*)input);
    k_wAB<<<2048, 256>>>(swA, swB, slog, tids);
    k_weff<<<NB * 16, 256>>>(weight);
    k_gemm<<<dim3(OUTF / BN, MTOT / BM), 128, SMEM_TOTAL>>>(bias, out);
}

// round 11
// speedup vs baseline: 1.0283x; 1.0283x over previous
#include <cuda_runtime.h>
#include <cuda_fp16.h>
#include <cstdint>

#define DI __device__ __forceinline__

constexpr int NB = 16, SEQ = 4096, INF = 1024, OUTF = 1024, RR = 16, NSK = 16;
constexpr int MTOT = NB * SEQ;                    // 65536
constexpr int NGROUP = 4;
constexpr int MGROUP = MTOT / NGROUP;             // 16384 rows (4 batches)

// ---------------- device scratch (allocation-free) ----------------
__device__ __half d_A16[(size_t)MTOT * INF];      // 134 MB
__device__ __half d_Weff[(size_t)NB * OUTF * INF];// 32 MB, [b][n][k] K-major
__device__ float  d_wA[NB * INF * RR];
__device__ float  d_wB[NB * RR * OUTF];

// ---------------- prep kernels ----------------
__global__ void k_convert(const float4* __restrict__ in, int blk_off) {
    size_t i = (((size_t)(blockIdx.x + blk_off)) * 256 + threadIdx.x) * 2;
    float4 v0 = in[i];
    float4 v1 = in[i + 1];
    __half2 h0 = __floats2half2_rn(v0.x, v0.y);
    __half2 h1 = __floats2half2_rn(v0.z, v0.w);
    __half2 h2 = __floats2half2_rn(v1.x, v1.y);
    __half2 h3 = __floats2half2_rn(v1.z, v1.w);
    uint4 u;
    u.x = *reinterpret_cast<uint32_t*>(&h0);
    u.y = *reinterpret_cast<uint32_t*>(&h1);
    u.z = *reinterpret_cast<uint32_t*>(&h2);
    u.w = *reinterpret_cast<uint32_t*>(&h3);
    reinterpret_cast<uint4*>(d_A16)[i >> 1] = u;
}

__global__ void k_wAB(const float* __restrict__ A, const float* __restrict__ Bm,
                      const float* __restrict__ sl, const int* __restrict__ tid_) {
    int gid = blockIdx.x * 256 + threadIdx.x;     // < 524288
    int hi = gid >> 18, e = gid & 262143;
    int b = e >> 14, j = e & 16383;
    __shared__ float lg[NSK];
    __shared__ float ssum;
    if (threadIdx.x < NSK) {
        float v = 1.f / (1.f + expf(-sl[tid_[b] * NSK + threadIdx.x]));
        lg[threadIdx.x] = v;
    }
    __syncthreads();
    if (threadIdx.x == 0) {
        float s = 0.f;
#pragma unroll
        for (int k = 0; k < NSK; ++k) s += lg[k];
        ssum = 1.f / (s + 1e-12f);
    }
    __syncthreads();
    const float* src = hi ? Bm : A;
    float acc = 0.f;
#pragma unroll
    for (int s = 0; s < NSK; ++s) acc += lg[s] * src[s * 16384 + j];
    acc *= ssum;
    if (hi) d_wB[e] = acc; else d_wA[e] = acc;
}

__global__ void __launch_bounds__(256) k_weff(const float* __restrict__ weight) {
    int b = blockIdx.x >> 4, ot = blockIdx.x & 15;
    __shared__ float wBs[64 * RR];                 // [o_local][r]
    for (int t = threadIdx.x; t < 64 * RR; t += 256) {
        int ol = t >> 4, r = t & 15;
        wBs[t] = d_wB[b * 16384 + r * OUTF + ot * 64 + ol];
    }
    __syncthreads();
    const int i0 = threadIdx.x * 4;
    float wa[4][RR];
#pragma unroll
    for (int ii = 0; ii < 4; ++ii) {
        float4 v0 = *(const float4*)(d_wA + b * 16384 + (i0 + ii) * RR);
        float4 v1 = *(const float4*)(d_wA + b * 16384 + (i0 + ii) * RR + 4);
        float4 v2 = *(const float4*)(d_wA + b * 16384 + (i0 + ii) * RR + 8);
        float4 v3 = *(const float4*)(d_wA + b * 16384 + (i0 + ii) * RR + 12);
        wa[ii][0]=v0.x; wa[ii][1]=v0.y; wa[ii][2]=v0.z; wa[ii][3]=v0.w;
        wa[ii][4]=v1.x; wa[ii][5]=v1.y; wa[ii][6]=v1.z; wa[ii][7]=v1.w;
        wa[ii][8]=v2.x; wa[ii][9]=v2.y; wa[ii][10]=v2.z; wa[ii][11]=v2.w;
        wa[ii][12]=v3.x; wa[ii][13]=v3.y; wa[ii][14]=v3.z; wa[ii][15]=v3.w;
    }
#pragma unroll 4
    for (int ol = 0; ol < 64; ++ol) {
        int o = ot * 64 + ol;
        float4 w = *(const float4*)(weight + (size_t)o * INF + i0);
        float acc[4] = {0.f, 0.f, 0.f, 0.f};
#pragma unroll
        for (int r = 0; r < RR; ++r) {
            float wb = wBs[ol * RR + r];
            acc[0] += wa[0][r] * wb; acc[1] += wa[1][r] * wb;
            acc[2] += wa[2][r] * wb; acc[3] += wa[3][r] * wb;
        }
        __half2 h0 = __floats2half2_rn(w.x + acc[0] * (1.f / RR), w.y + acc[1] * (1.f / RR));
        __half2 h1 = __floats2half2_rn(w.z + acc[2] * (1.f / RR), w.w + acc[3] * (1.f / RR));
        uint2 u;
        u.x = *reinterpret_cast<uint32_t*>(&h0);
        u.y = *reinterpret_cast<uint32_t*>(&h1);
        *reinterpret_cast<uint2*>(d_Weff + (size_t)b * (OUTF * INF) + (size_t)o * INF + i0) = u;
    }
}

// ---------------- GEMM config (R8 best: 376us) ----------------
constexpr int BM = 128, BN = 128, BK = 64;        // K chunk = 64 halfs = 128 B rows
constexpr int NCHUNK = INF / BK;                  // 16
constexpr int STAGE_BYTES = 32768;                // A 16K + B 16K
constexpr int SM_B = 16384;
constexpr int SMEM_TOTAL = 1024 + 3 * STAGE_BYTES;   // 99328 (2 CTAs/SM)

DI uint32_t s2u(const void* p) {
    uint32_t a;
    asm("{ .reg .u64 t; cvta.to.shared.u64 t, %1; cvt.u32.u64 %0, t; }" : "=r"(a) : "l"(p));
    return a;
}
DI void cp16(uint32_t dst, const void* src) {
    asm volatile("cp.async.cg.shared.global [%0], [%1], 16;" :: "r"(dst), "l"(src));
}
DI void cp_commit() { asm volatile("cp.async.commit_group;" ::: "memory"); }
template <int N> DI void cp_wait() { asm volatile("cp.async.wait_group %0;" :: "n"(N) : "memory"); }

DI void ldsm4(uint32_t addr, uint32_t* r) {
    asm volatile("ldmatrix.sync.aligned.m8n8.x4.shared.b16 {%0,%1,%2,%3}, [%4];"
                 : "=r"(r[0]), "=r"(r[1]), "=r"(r[2]), "=r"(r[3]) : "r"(addr));
}
DI void mma16816(float* c, const uint32_t* a, const uint32_t* b) {
    asm volatile(
        "mma.sync.aligned.m16n8k16.row.col.f32.f16.f16.f32 "
        "{%0,%1,%2,%3}, {%4,%5,%6,%7}, {%8,%9}, {%0,%1,%2,%3};"
        : "+f"(c[0]), "+f"(c[1]), "+f"(c[2]), "+f"(c[3])
        : "r"(a[0]), "r"(a[1]), "r"(a[2]), "r"(a[3]), "r"(b[0]), "r"(b[1]));
}

DI void fill_stage(uint32_t stg, const __half* Aptr, const __half* Bptr, int tid) {
#pragma unroll
    for (int j = 0; j < 8; ++j) {
        int idx = tid + j * 128;
        int row = idx >> 3, seg = idx & 7;
        uint32_t off = row * 128 + ((seg * 16) ^ ((row & 7) << 4));
        cp16(stg + off, Aptr + row * 1024 + seg * 8);
    }
#pragma unroll
    for (int j = 0; j < 8; ++j) {
        int idx = tid + j * 128;
        int row = idx >> 3, seg = idx & 7;
        uint32_t off = row * 128 + ((seg * 16) ^ ((row & 7) << 4));
        cp16(stg + SM_B + off, Bptr + row * 1024 + seg * 8);
    }
    cp_commit();
}

__global__ void __launch_bounds__(128, 2)
k_gemm(const float* __restrict__ bias, float* __restrict__ out, int m_base) {
    extern __shared__ char smem_raw[];
    uint32_t sb = (s2u(smem_raw) + 1023u) & ~1023u;
    const int tid = threadIdx.x, lane = tid & 31, w = tid >> 5;
    const int wm = w >> 1, wn = w & 1;            // warp tile 64x64 in 2x2 grid
    const int m0 = m_base + blockIdx.y * BM;
    const int n0 = blockIdx.x * BN;
    const int b  = m0 >> 12;

    const __half* Abase = d_A16 + (size_t)m0 * INF;
    const __half* Bbase = d_Weff + (size_t)b * (OUTF * INF) + (size_t)n0 * INF;

    fill_stage(sb, Abase, Bbase, tid);
    fill_stage(sb + STAGE_BYTES, Abase + BK, Bbase + BK, tid);

    float c[4][8][4];
#pragma unroll
    for (int i = 0; i < 4; ++i)
#pragma unroll
        for (int j = 0; j < 8; ++j)
#pragma unroll
            for (int q = 0; q < 4; ++q) c[i][j][q] = 0.f;

    const int a_row = wm * 64 + (lane & 15);                      // + mt*16
    const int a_kb  = (lane >> 4) * 16;
    const int b_row = wn * 64 + ((lane >> 4) << 3) + (lane & 7);  // + p*16
    const int b_kb  = ((lane >> 3) & 1) * 16;

    int st = 0, fs = 2;
#pragma unroll 1
    for (int i = 0; i < NCHUNK; ++i) {
        if (i < NCHUNK - 1) cp_wait<1>();
        else cp_wait<0>();
        __syncthreads();

        if (i + 2 < NCHUNK)
            fill_stage(sb + fs * STAGE_BYTES,
                       Abase + (i + 2) * BK, Bbase + (i + 2) * BK, tid);

        uint32_t as = sb + st * STAGE_BYTES;
        uint32_t bs = as + SM_B;

#pragma unroll
        for (int kk = 0; kk < 4; ++kk) {
            uint32_t af[4][4], bf[8][2];
#pragma unroll
            for (int mt = 0; mt < 4; ++mt) {
                int row = a_row + mt * 16;
                ldsm4(as + row * 128 + ((kk * 32 + a_kb) ^ ((row & 7) << 4)), af[mt]);
            }
#pragma unroll
            for (int p = 0; p < 4; ++p) {
                int row = b_row + p * 16;
                uint32_t r[4];
                ldsm4(bs + row * 128 + ((kk * 32 + b_kb) ^ ((row & 7) << 4)), r);
                bf[p * 2][0] = r[0]; bf[p * 2][1] = r[1];
                bf[p * 2 + 1][0] = r[2]; bf[p * 2 + 1][1] = r[3];
            }
#pragma unroll
            for (int mt = 0; mt < 4; ++mt)
#pragma unroll
                for (int nt = 0; nt < 8; ++nt)
                    mma16816(c[mt][nt], af[mt], bf[nt]);
        }
        st = (st == 2) ? 0 : st + 1;
        fs = (fs == 2) ? 0 : fs + 1;
    }

    // ---- epilogue ----
#pragma unroll
    for (int mt = 0; mt < 4; ++mt) {
        int r0 = m0 + wm * 64 + mt * 16 + (lane >> 2);
#pragma unroll
        for (int nt = 0; nt < 8; ++nt) {
            int cn = n0 + wn * 64 + nt * 8 + (lane & 3) * 2;
            float bx = __ldg(bias + cn), by = __ldg(bias + cn + 1);
            float2 v0 = make_float2(c[mt][nt][0] + bx, c[mt][nt][1] + by);
            float2 v1 = make_float2(c[mt][nt][2] + bx, c[mt][nt][3] + by);
            *reinterpret_cast<float2*>(out + (size_t)r0 * OUTF + cn) = v0;
            *reinterpret_cast<float2*>(out + (size_t)(r0 + 8) * OUTF + cn) = v1;
        }
    }
}

// ---------------- launch: minimal 2-stream fork/join ----------------
extern "C" void kernel_launch(void* const* d_in, const int* in_sizes, int n_in,
                              void* d_out, int out_size) {
    const float* input  = (const float*)d_in[0];
    const float* slog   = (const float*)d_in[1];
    const float* weight = (const float*)d_in[2];
    const float* bias   = (const float*)d_in[3];
    const float* swA    = (const float*)d_in[4];
    const float* swB    = (const float*)d_in[5];
    const int*   tids   = (const int*)d_in[6];
    float* out = (float*)d_out;

    static cudaStream_t s_conv = nullptr;
    static cudaEvent_t ev_fork, ev_conv[NGROUP];
    if (!s_conv) {
        cudaStreamCreateWithFlags(&s_conv, cudaStreamNonBlocking);
        cudaEventCreateWithFlags(&ev_fork, cudaEventDisableTiming);
        for (int g = 0; g < NGROUP; ++g)
            cudaEventCreateWithFlags(&ev_conv[g], cudaEventDisableTiming);
        cudaFuncSetAttribute(k_gemm, cudaFuncAttributeMaxDynamicSharedMemorySize, SMEM_TOTAL);
    }

    // fork: side stream branches off the capture (main) stream
    cudaEventRecord(ev_fork, 0);
    cudaStreamWaitEvent(s_conv, ev_fork, 0);

    // side: per-group converts
    for (int g = 0; g < NGROUP; ++g) {
        k_convert<<<8192, 256, 0, s_conv>>>((const float4*)input, g * 8192);
        cudaEventRecord(ev_conv[g], s_conv);
    }

    // main: routing + effective weights (overlaps conv g0)
    k_wAB<<<2048, 256>>>(swA, swB, slog, tids);
    k_weff<<<NB * 16, 256>>>(weight);

    // main: group GEMMs back-to-back; each gated on its convert.
    // gemm(g3)'s wait on ev_conv[3] (side stream's last node) closes the fork.
    for (int g = 0; g < NGROUP; ++g) {
        cudaStreamWaitEvent(0, ev_conv[g], 0);
        k_gemm<<<dim3(OUTF / BN, MGROUP / BM), 128, SMEM_TOTAL>>>(bias, out, g * MGROUP);
    }
}